// round 2
// baseline (speedup 1.0000x reference)
#include <cuda_runtime.h>
#include <math.h>

// CharRNN fused persistent kernel.
// B=512, L=1024, E=32, H=128, V=32.
// 128 CTAs x 256 threads; CTA owns 4 batch rows for the whole sequence.
// Thread (g = tid>>7, j = tid&127): column j of W_hh in registers (i-pair packed
// as f32x2), rows {2g, 2g+1}. Hidden state exchanged via shared memory.

#define ULL unsigned long long

__device__ __forceinline__ ULL ffma2(ULL a, ULL b, ULL c) {
    ULL d;
    asm("fma.rn.f32x2 %0, %1, %2, %3;" : "=l"(d) : "l"(a), "l"(b), "l"(c));
    return d;
}
__device__ __forceinline__ ULL pack2(float lo, float hi) {
    ULL d;
    asm("mov.b64 %0, {%1, %2};" : "=l"(d) : "f"(lo), "f"(hi));
    return d;
}
__device__ __forceinline__ float sum2(ULL a) {
    float lo, hi;
    asm("mov.b64 {%0, %1}, %2;" : "=f"(lo), "=f"(hi) : "l"(a));
    return lo + hi;
}

__global__ void __launch_bounds__(256, 1) charrnn_kernel(
    const int*   __restrict__ x,      // [512][1024]
    const float* __restrict__ emb,    // [32][32]
    const float* __restrict__ Wxh,    // [32][128]
    const float* __restrict__ Whh,    // [128][128]
    const float* __restrict__ bh,     // [128]
    const float* __restrict__ Why,    // [128][32]
    const float* __restrict__ by_g,   // [32]
    float*       __restrict__ out)    // logits [512][1024][32] ++ hidden [512][128]
{
    __shared__ __align__(16) float table[32 * 128];   // xh lookup: [token][j]
    __shared__ __align__(16) ULL   wyp[64 * 32];      // W_hy i-pair packed: [i/2][v]
    __shared__ __align__(16) float hpl[4 * 128];      // hidden state [row][i]
    __shared__ int   xs[4 * 128];                     // token chunk [row][tloc]
    __shared__ float bys[32];

    const int tid = threadIdx.x;
    const int j   = tid & 127;
    const int g   = tid >> 7;          // 0/1 -> rows 2g, 2g+1
    const int r0  = blockIdx.x * 4;    // first batch row of this CTA

    // ---- one-time init ----
    // xh table: table[c][j] = b_h[j] + sum_e emb[c][e] * Wxh[e][j]
    for (int c = g * 16; c < g * 16 + 16; c++) {
        float s = bh[j];
        #pragma unroll 8
        for (int e = 0; e < 32; e++)
            s = fmaf(emb[c * 32 + e], Wxh[e * 128 + j], s);
        table[c * 128 + j] = s;
    }
    // W_hy packed over i-pairs
    for (int idx = tid; idx < 64 * 32; idx += 256) {
        int k = idx >> 5, v = idx & 31;
        wyp[idx] = pack2(Why[(2 * k) * 32 + v], Why[(2 * k + 1) * 32 + v]);
    }
    if (tid < 32) bys[tid] = by_g[tid];
    if (g == 0) {
        hpl[j] = 0.f; hpl[128 + j] = 0.f; hpl[256 + j] = 0.f; hpl[384 + j] = 0.f;
    }
    // W_hh column j in registers, i-pair packed: Wreg[k] = {W[2k][j], W[2k+1][j]}
    ULL Wreg[64];
    #pragma unroll
    for (int k = 0; k < 64; k++)
        Wreg[k] = pack2(Whh[(2 * k) * 128 + j], Whh[(2 * k + 1) * 128 + j]);
    __syncthreads();

    const int ra = 2 * g, rb = 2 * g + 1;
    const float* hA = hpl + ra * 128;
    const float* hB = hpl + rb * 128;

    for (int t = 0; t < 1024; t++) {
        const int tloc = t & 127;
        if (tloc == 0) {
            // refill token chunk (safe: all prior readers of xs are pre-bar1 of t-1)
            for (int s = tid; s < 512; s += 256)
                xs[s] = x[(r0 + (s >> 7)) * 1024 + t + (s & 127)];
            __syncthreads();
        }

        // ---- Phase A: newh[r][j] = tanh(xh + sum_i h[r][i]*Whh[i][j]) ----
        const int ca = xs[ra * 128 + tloc];
        const int cb = xs[rb * 128 + tloc];
        ULL acc_a = pack2(table[ca * 128 + j], 0.0f);
        ULL acc_b = pack2(table[cb * 128 + j], 0.0f);
        #pragma unroll
        for (int kk = 0; kk < 32; kk++) {
            ulonglong2 ha = *(const ulonglong2*)(hA + 4 * kk);  // {h[4kk],h[4kk+1]},{h[4kk+2],h[4kk+3]}
            ulonglong2 hb = *(const ulonglong2*)(hB + 4 * kk);
            acc_a = ffma2(ha.x, Wreg[2 * kk],     acc_a);
            acc_b = ffma2(hb.x, Wreg[2 * kk],     acc_b);
            acc_a = ffma2(ha.y, Wreg[2 * kk + 1], acc_a);
            acc_b = ffma2(hb.y, Wreg[2 * kk + 1], acc_b);
        }
        float na = tanhf(sum2(acc_a));
        float nb = tanhf(sum2(acc_b));

        __syncthreads();                 // bar1: everyone done reading old h
        hpl[ra * 128 + j] = na;
        hpl[rb * 128 + j] = nb;
        __syncthreads();                 // bar2: new h visible

        // ---- Phase C: logits[b][t][v] = by[v] + sum_i h[rr][i]*Why[i][v] ----
        if (tid < 128) {
            const int v  = tid & 31;
            const int rr = tid >> 5;
            const float* hr = hpl + rr * 128;
            ULL la = pack2(bys[v], 0.0f);
            ULL lb = pack2(0.0f, 0.0f);
            #pragma unroll
            for (int kk = 0; kk < 16; kk++) {
                ulonglong2 h0 = *(const ulonglong2*)(hr + 8 * kk);
                la = ffma2(h0.x, wyp[(4 * kk + 0) * 32 + v], la);
                lb = ffma2(h0.y, wyp[(4 * kk + 1) * 32 + v], lb);
                ulonglong2 h1 = *(const ulonglong2*)(hr + 8 * kk + 4);
                la = ffma2(h1.x, wyp[(4 * kk + 2) * 32 + v], la);
                lb = ffma2(h1.y, wyp[(4 * kk + 3) * 32 + v], lb);
            }
            out[(size_t)((r0 + rr) * 1024 + t) * 32 + v] = sum2(la) + sum2(lb);
        }
    }

    // ---- final hidden state ----
    if (g == 0) {
        #pragma unroll
        for (int r = 0; r < 4; r++)
            out[16777216u + (size_t)(r0 + r) * 128 + j] = hpl[r * 128 + j];
    }
}

extern "C" void kernel_launch(void* const* d_in, const int* in_sizes, int n_in,
                              void* d_out, int out_size) {
    (void)in_sizes; (void)n_in; (void)out_size;
    const int*   x   = (const int*)d_in[0];
    const float* emb = (const float*)d_in[1];
    const float* Wxh = (const float*)d_in[2];
    const float* Whh = (const float*)d_in[3];
    const float* bh  = (const float*)d_in[4];
    const float* Why = (const float*)d_in[5];
    const float* by  = (const float*)d_in[6];
    float* out = (float*)d_out;

    charrnn_kernel<<<128, 256>>>(x, emb, Wxh, Whh, bh, Why, by, out);
}

// round 3
// speedup vs baseline: 1.1307x; 1.1307x over previous
#include <cuda_runtime.h>
#include <math.h>

// CharRNN fused persistent kernel, round 3.
// B=512, L=1024, E=32, H=128, V=32.  128 CTAs x 256 threads, 4 batch rows/CTA.
// Pipelined: per barrier period t we run Phase A(t) (recurrence), Phase C
// partials(t-1) (logit i-partials, W_hy register-resident), reduce(t-2) + STG.
// One __syncthreads per step; h and partial buffers double-buffered.

#define ULL unsigned long long

__device__ __forceinline__ ULL ffma2(ULL a, ULL b, ULL c) {
    ULL d;
    asm("fma.rn.f32x2 %0, %1, %2, %3;" : "=l"(d) : "l"(a), "l"(b), "l"(c));
    return d;
}
__device__ __forceinline__ ULL pack2(float lo, float hi) {
    ULL d;
    asm("mov.b64 %0, {%1, %2};" : "=l"(d) : "f"(lo), "f"(hi));
    return d;
}
__device__ __forceinline__ float sum2(ULL a) {
    float lo, hi;
    asm("mov.b64 {%0, %1}, %2;" : "=f"(lo), "=f"(hi) : "l"(a));
    return lo + hi;
}

__global__ void __launch_bounds__(256, 1) charrnn_kernel(
    const int*   __restrict__ x,      // [512][1024]
    const float* __restrict__ emb,    // [32][32]
    const float* __restrict__ Wxh,    // [32][128]
    const float* __restrict__ Whh,    // [128][128]
    const float* __restrict__ bh,     // [128]
    const float* __restrict__ Why,    // [128][32]
    const float* __restrict__ by_g,   // [32]
    float*       __restrict__ out)    // logits [512][1024][32] ++ hidden [512][128]
{
    __shared__ __align__(16) float table[32 * 128];   // xh lookup: [token][j]
    __shared__ __align__(16) float hbuf[2][4 * 128];  // hidden state, ping-pong
    __shared__ __align__(16) float pbuf[2][4 * 256];  // logit partials [r][p*32+v]
    __shared__ int   xs[4 * 128];                     // token chunk [row][tloc]
    __shared__ float bys[32];

    const int tid = threadIdx.x;
    const int j   = tid & 127;
    const int g   = tid >> 7;          // 0/1 -> rows 2g, 2g+1
    const int v   = tid & 31;          // logit vocab lane
    const int p   = tid >> 5;          // i-range selector: i in [16p, 16p+16)
    const int r0  = blockIdx.x * 4;    // first batch row of this CTA

    // ---- one-time init ----
    // xh table: table[c][j] = b_h[j] + sum_e emb[c][e] * Wxh[e][j]
    for (int c = g * 16; c < g * 16 + 16; c++) {
        float s = bh[j];
        #pragma unroll 8
        for (int e = 0; e < 32; e++)
            s = fmaf(emb[c * 32 + e], Wxh[e * 128 + j], s);
        table[c * 128 + j] = s;
    }
    if (tid < 32) bys[tid] = by_g[tid];
    // h_{-1} = 0 lives in parity buffer 1
    hbuf[1][tid] = 0.f; hbuf[1][tid + 256] = 0.f;

    // W_hy register-resident: thread (p,v) needs pairs k = 8p..8p+7
    ULL Wy[8];
    #pragma unroll
    for (int kk = 0; kk < 8; kk++) {
        int k = 8 * p + kk;
        Wy[kk] = pack2(Why[(2 * k) * 32 + v], Why[(2 * k + 1) * 32 + v]);
    }
    // W_hh column j in registers, i-pair packed
    ULL Wreg[64];
    #pragma unroll
    for (int k = 0; k < 64; k++)
        Wreg[k] = pack2(Whh[(2 * k) * 128 + j], Whh[(2 * k + 1) * 128 + j]);

    const int ra = 2 * g, rb = 2 * g + 1;

    for (int t = 0; t < 1026; t++) {
        __syncthreads();
        const int bw = t & 1;        // parity of h_t / pbuf slot for reduce(t-2)
        const int br = bw ^ 1;       // parity of h_{t-1} / pbuf slot for partials(t-1)

        // ---- Phase A(t): h_t = tanh(xh[token_t] + h_{t-1} @ W_hh) ----
        if (t < 1024) {
            const int tloc = t & 127;
            if (tloc == 0) {
                for (int s = tid; s < 512; s += 256)
                    xs[s] = x[(r0 + (s >> 7)) * 1024 + t + (s & 127)];
                __syncthreads();
            }
            const float* hA = hbuf[br] + ra * 128;
            const float* hB = hbuf[br] + rb * 128;
            const int ca = xs[ra * 128 + tloc];
            const int cb = xs[rb * 128 + tloc];
            ULL acc_a = pack2(table[ca * 128 + j], 0.0f);
            ULL acc_b = pack2(table[cb * 128 + j], 0.0f);
            #pragma unroll
            for (int kk = 0; kk < 32; kk++) {
                ulonglong2 ha = *(const ulonglong2*)(hA + 4 * kk);
                ulonglong2 hb = *(const ulonglong2*)(hB + 4 * kk);
                acc_a = ffma2(ha.x, Wreg[2 * kk],     acc_a);
                acc_b = ffma2(hb.x, Wreg[2 * kk],     acc_b);
                acc_a = ffma2(ha.y, Wreg[2 * kk + 1], acc_a);
                acc_b = ffma2(hb.y, Wreg[2 * kk + 1], acc_b);
            }
            hbuf[bw][ra * 128 + j] = tanhf(sum2(acc_a));
            hbuf[bw][rb * 128 + j] = tanhf(sum2(acc_b));
        }

        // ---- Phase C partials(t-1): all 256 threads, W_hy in registers ----
        if (t >= 1 && t < 1025) {
            const float* h  = hbuf[br];          // h_{t-1}
            float*       pb = pbuf[br];
            #pragma unroll
            for (int r = 0; r < 4; r++) {
                const ulonglong2* hp = (const ulonglong2*)(h + r * 128 + 16 * p);
                ulonglong2 q0 = hp[0];
                ulonglong2 q1 = hp[1];
                ULL a = ffma2(q0.x, Wy[0], 0ull);
                a = ffma2(q0.y, Wy[1], a);
                a = ffma2(q1.x, Wy[2], a);
                a = ffma2(q1.y, Wy[3], a);
                ulonglong2 q2 = hp[2];
                ulonglong2 q3 = hp[3];
                a = ffma2(q2.x, Wy[4], a);
                a = ffma2(q2.y, Wy[5], a);
                a = ffma2(q3.x, Wy[6], a);
                a = ffma2(q3.y, Wy[7], a);
                pb[r * 256 + p * 32 + v] = sum2(a);
            }
        }

        // ---- Reduce(t-2): 128 threads fold 8 partials, add bias, store ----
        if (t >= 2 && tid < 128) {
            const int rr = tid >> 5;
            const float* pb = pbuf[bw];          // (t-2) parity == bw
            float s = bys[v];
            #pragma unroll
            for (int q = 0; q < 8; q++)
                s += pb[rr * 256 + q * 32 + v];
            out[(size_t)((r0 + rr) * 1024 + (t - 2)) * 32 + v] = s;
        }
    }

    // ---- final hidden state: h_1023 lives in parity buffer 1 ----
    if (tid < 128) {
        #pragma unroll
        for (int r = 0; r < 4; r++)
            out[16777216u + (size_t)(r0 + r) * 128 + j] = hbuf[1][r * 128 + j];
    }
}

extern "C" void kernel_launch(void* const* d_in, const int* in_sizes, int n_in,
                              void* d_out, int out_size) {
    (void)in_sizes; (void)n_in; (void)out_size;
    const int*   x   = (const int*)d_in[0];
    const float* emb = (const float*)d_in[1];
    const float* Wxh = (const float*)d_in[2];
    const float* Whh = (const float*)d_in[3];
    const float* bh  = (const float*)d_in[4];
    const float* Why = (const float*)d_in[5];
    const float* by  = (const float*)d_in[6];
    float* out = (float*)d_out;

    charrnn_kernel<<<128, 256>>>(x, emb, Wxh, Whh, bh, Why, by, out);
}

// round 6
// speedup vs baseline: 1.2203x; 1.0793x over previous
#include <cuda_runtime.h>
#include <math.h>

// CharRNN fused persistent kernel, round 4.
// B=512, L=1024, E=32, H=128, V=32.
// 256 CTAs x 128 threads, 2 batch rows per CTA, 2 CTAs resident per SM
// (independent barriers -> latency hiding). Whh column j register-resident
// (i-pair packed f32x2). Pipelined: A(t) | C-partials(t-1) | reduce+STG(t-2),
// one __syncthreads per step, double-buffered h and partials.

#define ULL unsigned long long

__device__ __forceinline__ ULL ffma2(ULL a, ULL b, ULL c) {
    ULL d;
    asm("fma.rn.f32x2 %0, %1, %2, %3;" : "=l"(d) : "l"(a), "l"(b), "l"(c));
    return d;
}
__device__ __forceinline__ ULL pack2(float lo, float hi) {
    ULL d;
    asm("mov.b64 %0, {%1, %2};" : "=l"(d) : "f"(lo), "f"(hi));
    return d;
}
__device__ __forceinline__ float sum2(ULL a) {
    float lo, hi;
    asm("mov.b64 {%0, %1}, %2;" : "=f"(lo), "=f"(hi) : "l"(a));
    return lo + hi;
}
// Stable fast tanh: 1 - 2/(exp(2x)+1).  x->-inf: expf->0 -> -1; x->+inf: rcp(inf)=0 -> 1.
__device__ __forceinline__ float fast_tanh(float x) {
    return 1.0f - __fdividef(2.0f, __expf(2.0f * x) + 1.0f);
}

__global__ void __launch_bounds__(128, 2) charrnn_kernel(
    const int*   __restrict__ x,      // [512][1024]
    const float* __restrict__ emb,    // [32][32]
    const float* __restrict__ Wxh,    // [32][128]
    const float* __restrict__ Whh,    // [128][128]
    const float* __restrict__ bh,     // [128]
    const float* __restrict__ Why,    // [128][32]
    const float* __restrict__ by_g,   // [32]
    float*       __restrict__ out)    // logits [512][1024][32] ++ hidden [512][128]
{
    __shared__ __align__(16) float table[32 * 128];   // xh lookup: [token][j]
    __shared__ __align__(16) float hbuf[2][2 * 128];  // hidden state, ping-pong
    __shared__ __align__(16) float pbuf[2][2 * 128];  // logit partials [r][p*32+v]
    __shared__ int   xs[2 * 128];                     // token chunk [row][tloc]
    __shared__ float bys[32];

    const int tid = threadIdx.x;      // 0..127
    const int j   = tid;              // W_hh column / hidden index
    const int v   = tid & 31;         // logit vocab lane
    const int p   = tid >> 5;         // i-range selector: i in [32p, 32p+32)
    const int r0  = blockIdx.x * 2;   // first batch row of this CTA

    // ---- one-time init ----
    for (int c = 0; c < 32; c++) {
        float s = bh[j];
        #pragma unroll 8
        for (int e = 0; e < 32; e++)
            s = fmaf(emb[c * 32 + e], Wxh[e * 128 + j], s);
        table[c * 128 + j] = s;
    }
    if (tid < 32) bys[tid] = by_g[tid];
    // h_{-1} = 0 lives in parity buffer 1
    hbuf[1][tid] = 0.f; hbuf[1][tid + 128] = 0.f;

    // W_hy register-resident: thread (p,v) covers i-pairs k = 16p..16p+15
    ULL Wy[16];
    #pragma unroll
    for (int kk = 0; kk < 16; kk++) {
        int k = 16 * p + kk;
        Wy[kk] = pack2(Why[(2 * k) * 32 + v], Why[(2 * k + 1) * 32 + v]);
    }
    // W_hh column j, i-pair packed
    ULL Wreg[64];
    #pragma unroll
    for (int k = 0; k < 64; k++)
        Wreg[k] = pack2(Whh[(2 * k) * 128 + j], Whh[(2 * k + 1) * 128 + j]);

    for (int t = 0; t < 1026; t++) {
        __syncthreads();
        const int bw = t & 1;        // parity of h_t / pbuf slot for reduce(t-2)
        const int br = bw ^ 1;       // parity of h_{t-1} / pbuf slot for partials(t-1)

        // ---- Phase A(t): h_t = tanh(xh[token_t] + h_{t-1} @ W_hh) ----
        if (t < 1024) {
            const int tloc = t & 127;
            if (tloc == 0) {
                for (int s = tid; s < 256; s += 128)
                    xs[s] = x[(r0 + (s >> 7)) * 1024 + t + (s & 127)];
                __syncthreads();
            }
            const float* hA = hbuf[br];
            const float* hB = hbuf[br] + 128;
            const int ca = xs[tloc];
            const int cb = xs[128 + tloc];
            // 2 accumulator chains per row for ILP (32-deep each)
            ULL a0 = pack2(table[ca * 128 + j], 0.0f), a1 = 0ull;
            ULL b0 = pack2(table[cb * 128 + j], 0.0f), b1 = 0ull;
            #pragma unroll
            for (int kk = 0; kk < 32; kk++) {
                ulonglong2 ha = *(const ulonglong2*)(hA + 4 * kk);
                ulonglong2 hb = *(const ulonglong2*)(hB + 4 * kk);
                a0 = ffma2(ha.x, Wreg[2 * kk],     a0);
                b0 = ffma2(hb.x, Wreg[2 * kk],     b0);
                a1 = ffma2(ha.y, Wreg[2 * kk + 1], a1);
                b1 = ffma2(hb.y, Wreg[2 * kk + 1], b1);
            }
            hbuf[bw][j]       = fast_tanh(sum2(a0) + sum2(a1));
            hbuf[bw][128 + j] = fast_tanh(sum2(b0) + sum2(b1));
        }

        // ---- Phase C partials(t-1): thread (p,v) does i in [32p,32p+32) ----
        if (t >= 1 && t < 1025) {
            const float* h  = hbuf[br];          // h_{t-1}
            float*       pb = pbuf[br];
            #pragma unroll
            for (int r = 0; r < 2; r++) {
                const ulonglong2* hp = (const ulonglong2*)(h + r * 128 + 32 * p);
                ULL s0 = 0ull, s1 = 0ull;
                #pragma unroll
                for (int q = 0; q < 8; q++) {
                    ulonglong2 hh = hp[q];
                    s0 = ffma2(hh.x, Wy[2 * q],     s0);
                    s1 = ffma2(hh.y, Wy[2 * q + 1], s1);
                }
                pb[r * 128 + p * 32 + v] = sum2(s0) + sum2(s1);
            }
        }

        // ---- Reduce(t-2): 64 threads fold 4 partials, add bias, store ----
        if (t >= 2 && tid < 64) {
            const int rr = tid >> 5;
            const float* pb = pbuf[bw];          // (t-2) parity == bw
            float s = bys[v];
            #pragma unroll
            for (int q = 0; q < 4; q++)
                s += pb[rr * 128 + q * 32 + v];
            out[(size_t)((r0 + rr) * 1024 + (t - 2)) * 32 + v] = s;
        }
    }

    // ---- final hidden state: h_1023 lives in parity buffer 1 ----
    #pragma unroll
    for (int r = 0; r < 2; r++)
        out[16777216u + (size_t)(r0 + r) * 128 + j] = hbuf[1][r * 128 + j];
}

extern "C" void kernel_launch(void* const* d_in, const int* in_sizes, int n_in,
                              void* d_out, int out_size) {
    (void)in_sizes; (void)n_in; (void)out_size;
    const int*   x   = (const int*)d_in[0];
    const float* emb = (const float*)d_in[1];
    const float* Wxh = (const float*)d_in[2];
    const float* Whh = (const float*)d_in[3];
    const float* bh  = (const float*)d_in[4];
    const float* Why = (const float*)d_in[5];
    const float* by  = (const float*)d_in[6];
    float* out = (float*)d_out;

    charrnn_kernel<<<256, 128>>>(x, emb, Wxh, Whh, bh, Why, by, out);
}